// round 4
// baseline (speedup 1.0000x reference)
#include <cuda_runtime.h>
#include <cuda_bf16.h>

// ConvSpatialPropagationNet_71949292143069
//
// Math (verified on HW in R1, rel_err 6.1e-8): the reference's propagation
// multiplies the padded gate tensor by the padded depth ELEMENTWISE (no
// neighbor gather), so each step is d <- (1-G)*raw + G*d with d0 = raw,
// whose fixed point is d = raw = blur_depth. Output = copy of d_in[1].
//
// R1 ncu: DRAM 25.4% of peak (1991 GB/s), issue 10.6% -> latency-bound at
// MLP=1/thread. This version: 4 independent front-batched LDG.128 per thread
// (MLP=4) + streaming cache hints (.cs) for the zero-reuse stream. Each block
// moves a contiguous 16 KB tile (1024 float4); N4 = 856,064 = 836 * 1024
// exactly, so all predicates are uniformly true (no divergence, no tail).

__global__ void __launch_bounds__(256, 1)
cspn_copy4_kernel(const float4* __restrict__ in,
                  float4* __restrict__ out,
                  int n4) {
    int base = blockIdx.x * 1024 + threadIdx.x;

    int i0 = base;
    int i1 = base + 256;
    int i2 = base + 512;
    int i3 = base + 768;

    float4 a, b, c, d;
    bool p0 = i0 < n4, p1 = i1 < n4, p2 = i2 < n4, p3 = i3 < n4;

    if (p0) a = __ldcs(in + i0);
    if (p1) b = __ldcs(in + i1);
    if (p2) c = __ldcs(in + i2);
    if (p3) d = __ldcs(in + i3);

    if (p0) __stcs(out + i0, a);
    if (p1) __stcs(out + i1, b);
    if (p2) __stcs(out + i2, c);
    if (p3) __stcs(out + i3, d);
}

extern "C" void kernel_launch(void* const* d_in, const int* in_sizes, int n_in,
                              void* d_out, int out_size) {
    // Inputs (metadata order): guidance, blur_depth, sparse_depth, sum_w
    const float* blur_depth = (const float*)d_in[1];
    float* out = (float*)d_out;

    int n  = in_sizes[1];              // 3,424,256
    int n4 = n >> 2;                   // 856,064 float4
    int per_block = 1024;              // float4 per block (16 KB)
    int blocks = (n4 + per_block - 1) / per_block;   // 836

    cspn_copy4_kernel<<<blocks, 256>>>((const float4*)blur_depth,
                                       (float4*)out, n4);
}